// round 2
// baseline (speedup 1.0000x reference)
#include <cuda_runtime.h>
#include <cuda_bf16.h>

// SpatialConv SCNN 4-direction recurrent conv, GB300 sm_103a.
// R2: f32x2 FFMA2 with zero packing overhead (dup-SMEM inputs, paired weight
// loads), ci-split reduction for the W-pass, pre-transposed weights.

#define BB 64
#define CC 128
#define HH 36
#define WW 100
#define KK 9

typedef unsigned long long u64;

__device__ float g_T[(size_t)BB * CC * WW * HH];     // transposed activations
__device__ float g_Wt[4][CC * CC * KK];              // weights as [ci][k][co]

__device__ __forceinline__ void ffma2(u64& d, u64 a, u64 b) {
    asm("fma.rn.f32x2 %0, %1, %2, %0;" : "+l"(d) : "l"(a), "l"(b));
}
__device__ __forceinline__ u64 pack2(float a, float b) {
    u64 r; asm("mov.b64 %0, {%1, %2};" : "=l"(r) : "f"(a), "f"(b)); return r;
}
__device__ __forceinline__ void unpack2(u64 v, float& a, float& b) {
    asm("mov.b64 {%0, %1}, %2;" : "=f"(a), "=f"(b) : "l"(v));
}

// Recurrence step on buffer [B, C, S, L]:
//   buf[b,co,s_dst,l] += relu(bias[co] + sum_{ci,k} w[co,ci,k]*buf[b,ci,s_src,l+k-4])
// Thread map: tid -> (cis, lg, cp). Each thread: 4 co (2 f32x2 pairs) x NL l,
// reducing over CC/CIS input channels; CIS partial sums combined in SMEM.
template <int L, int S, int CP, int LG, int NL, int LSPLIT, int CIS, int CIC, int MB>
__global__ __launch_bounds__(CP * LG * CIS, MB)
void step_kernel(float* __restrict__ buf, int s_src, int s_dst,
                 const float* __restrict__ wt, const float* __restrict__ bias)
{
    constexpr int CO_TILE = 4 * CP;
    constexpr int LW   = L / LSPLIT;
    constexpr int WIN  = LG * NL + 8;       // dup window incl. halo
    constexpr int NT   = CP * LG * CIS;
    constexpr int CI_PER = CC / CIS;
    constexpr int NCHUNK = CI_PER / CIC;
    constexpr int ROWS = CIS * CIC;
    static_assert(LG * NL == LW, "exact L coverage");

    __shared__ __align__(16) float2 in_d[ROWS][WIN];          // {x,x} duplicated
    __shared__ __align__(16) float  w_s[ROWS * KK * CO_TILE]; // [cis][i][k][co]

    const int tid = threadIdx.x;
    const int rr  = tid % (CP * LG);
    const int cis = tid / (CP * LG);
    const int cp  = rr % CP;
    const int lg  = rr / CP;
    const int b   = blockIdx.z;
    const int co_base = blockIdx.y * CO_TILE;
    const int l_base  = blockIdx.x * LW;

    // Accumulators: bias folded into cis==0 partials.
    u64 acc0[NL], acc1[NL];
    {
        float b0 = bias[co_base + 4 * cp + 0];
        float b1 = bias[co_base + 4 * cp + 1];
        float b2 = bias[co_base + 4 * cp + 2];
        float b3 = bias[co_base + 4 * cp + 3];
        u64 p01 = (cis == 0) ? pack2(b0, b1) : 0ull;
        u64 p23 = (cis == 0) ? pack2(b2, b3) : 0ull;
#pragma unroll
        for (int j = 0; j < NL; j++) { acc0[j] = p01; acc1[j] = p23; }
    }

    for (int cc = 0; cc < NCHUNK; cc++) {
        __syncthreads();
        // Stage input rows (duplicated floats), zero halo.
        for (int idx = tid; idx < ROWS * WIN; idx += NT) {
            int row = idx / WIN, j = idx % WIN;
            int ciI = row / CIC, i = row % CIC;
            int g = ciI * CI_PER + cc * CIC + i;
            int gl = l_base + j - 4;
            float v = 0.f;
            if (gl >= 0 && gl < L)
                v = buf[((size_t)(b * CC + g) * S + s_src) * L + gl];
            in_d[row][j] = make_float2(v, v);
        }
        // Stage weights (coalesced from pre-transposed [ci][k][co]).
        for (int idx = tid; idx < ROWS * KK * CO_TILE; idx += NT) {
            int co = idx % CO_TILE;
            int k  = (idx / CO_TILE) % KK;
            int i  = (idx / (CO_TILE * KK)) % CIC;
            int ciI = idx / (CO_TILE * KK * CIC);
            int g = ciI * CI_PER + cc * CIC + i;
            w_s[idx] = wt[((size_t)g * KK + k) * CC + co_base + co];
        }
        __syncthreads();

#pragma unroll 2
        for (int i = 0; i < CIC; i++) {
            const int row = cis * CIC + i;
            u64 xx[NL + 8];
            const u64* xr = (const u64*)&in_d[row][lg * NL];
#pragma unroll
            for (int t = 0; t < NL + 8; t++) xx[t] = xr[t];
            const float* wr = &w_s[(row * KK) * CO_TILE + 4 * cp];
#pragma unroll
            for (int k = 0; k < KK; k++) {
                ulonglong2 wv = *(const ulonglong2*)(wr + k * CO_TILE);
#pragma unroll
                for (int j = 0; j < NL; j++) {
                    ffma2(acc0[j], wv.x, xx[j + k]);
                    ffma2(acc1[j], wv.y, xx[j + k]);
                }
            }
        }
    }
    __syncthreads();

    // Cross-cis reduction through SMEM (reuse w_s region).
    float* red = w_s;  // (CIS-1)*CO_TILE*LW floats
    if (CIS > 1) {
        if (cis > 0) {
            float* p = red + (size_t)(cis - 1) * CO_TILE * LW;
#pragma unroll
            for (int j = 0; j < NL; j++) {
                int l = lg * NL + j;
                float a, b2, c, d;
                unpack2(acc0[j], a, b2); unpack2(acc1[j], c, d);
                p[(4 * cp + 0) * LW + l] = a;
                p[(4 * cp + 1) * LW + l] = b2;
                p[(4 * cp + 2) * LW + l] = c;
                p[(4 * cp + 3) * LW + l] = d;
            }
        }
        __syncthreads();
    }

    float* out_s = (float*)in_d;  // CO_TILE*LW floats
    if (cis == 0) {
#pragma unroll
        for (int j = 0; j < NL; j++) {
            int l = lg * NL + j;
            float a, b2, c, d;
            unpack2(acc0[j], a, b2); unpack2(acc1[j], c, d);
            if (CIS > 1) {
#pragma unroll
                for (int c2 = 1; c2 < CIS; c2++) {
                    const float* p = red + (size_t)(c2 - 1) * CO_TILE * LW;
                    a  += p[(4 * cp + 0) * LW + l];
                    b2 += p[(4 * cp + 1) * LW + l];
                    c  += p[(4 * cp + 2) * LW + l];
                    d  += p[(4 * cp + 3) * LW + l];
                }
            }
            out_s[(4 * cp + 0) * LW + l] = fmaxf(a, 0.f);
            out_s[(4 * cp + 1) * LW + l] = fmaxf(b2, 0.f);
            out_s[(4 * cp + 2) * LW + l] = fmaxf(c, 0.f);
            out_s[(4 * cp + 3) * LW + l] = fmaxf(d, 0.f);
        }
    }
    __syncthreads();

    for (int idx = tid; idx < CO_TILE * LW; idx += NT) {
        int co = idx / LW, l = idx % LW;
        buf[((size_t)(b * CC + co_base + co) * S + s_dst) * L + l_base + l] += out_s[idx];
    }
}

// Weight layout transform: [co][ci][k] -> [ci][k][co]
__global__ void prep_w(const float* __restrict__ w, float* __restrict__ wt) {
    int idx = blockIdx.x * 256 + threadIdx.x;
    if (idx < CC * CC * KK) {
        int co = idx / (CC * KK);
        int rem = idx % (CC * KK);
        int ci = rem / KK, k = rem % KK;
        wt[((size_t)ci * KK + k) * CC + co] = w[idx];
    }
}

// Transpose inner two dims: in [BC][R][Cc] -> out [BC][Cc][R]
__global__ void transpose_kernel(const float* __restrict__ in, float* __restrict__ out,
                                 int R, int Cc)
{
    __shared__ float tile[32][33];
    const int bc = blockIdx.z;
    const int c0 = blockIdx.x * 32;
    const int r0 = blockIdx.y * 32;
    const float* ip = in + (size_t)bc * R * Cc;
    float* op = out + (size_t)bc * R * Cc;
    const int tx = threadIdx.x, ty = threadIdx.y;

    for (int i = ty; i < 32; i += 8) {
        int r = r0 + i, c = c0 + tx;
        if (r < R && c < Cc) tile[i][tx] = ip[(size_t)r * Cc + c];
    }
    __syncthreads();
    for (int i = ty; i < 32; i += 8) {
        int c = c0 + i, r = r0 + tx;
        if (c < Cc && r < R) op[(size_t)c * R + r] = tile[tx][i];
    }
}

extern "C" void kernel_launch(void* const* d_in, const int* in_sizes, int n_in,
                              void* d_out, int out_size)
{
    const float* x   = (const float*)d_in[0];
    const float* w_d = (const float*)d_in[1];
    const float* b_d = (const float*)d_in[2];
    const float* w_u = (const float*)d_in[3];
    const float* b_u = (const float*)d_in[4];
    const float* w_r = (const float*)d_in[5];
    const float* b_r = (const float*)d_in[6];
    const float* w_l = (const float*)d_in[7];
    const float* b_l = (const float*)d_in[8];
    float* out = (float*)d_out;

    float* T = nullptr;
    cudaGetSymbolAddress((void**)&T, g_T);
    float* Wt = nullptr;
    cudaGetSymbolAddress((void**)&Wt, g_Wt);
    float* wt_d = Wt + 0 * (CC * CC * KK);
    float* wt_u = Wt + 1 * (CC * CC * KK);
    float* wt_r = Wt + 2 * (CC * CC * KK);
    float* wt_l = Wt + 3 * (CC * CC * KK);

    const int WG = (CC * CC * KK + 255) / 256;
    prep_w<<<WG, 256>>>(w_d, wt_d);
    prep_w<<<WG, 256>>>(w_u, wt_u);
    prep_w<<<WG, 256>>>(w_r, wt_r);
    prep_w<<<WG, 256>>>(w_l, wt_l);

    const size_t nbytes = (size_t)BB * CC * HH * WW * sizeof(float);
    cudaMemcpyAsync(out, x, nbytes, cudaMemcpyDeviceToDevice, 0);

    // ---- Down / Up: recurrence over H, conv along W (L=100, S=36) ----
    // <L,S,CP,LG,NL,LSPLIT,CIS,CIC,MB>: 512 blocks x 200 thr, exact coverage.
    dim3 gw(2, CC / 32, BB);
    for (int h = 1; h <= HH - 1; h++)
        step_kernel<WW, HH, 8, 25, 2, 2, 1, 16, 5><<<gw, 200>>>(out, h - 1, h, wt_d, b_d);
    for (int h = HH - 2; h >= 1; h--)
        step_kernel<WW, HH, 8, 25, 2, 2, 1, 16, 5><<<gw, 200>>>(out, h + 1, h, wt_u, b_u);

    // ---- Transpose [B,C,H,W] -> [B,C,W,H] ----
    {
        dim3 tb(32, 8);
        dim3 tg((WW + 31) / 32, (HH + 31) / 32, BB * CC);
        transpose_kernel<<<tg, tb>>>(out, T, HH, WW);
    }

    // ---- Right / Left: recurrence over W, conv along H (L=36, S=100) ----
    // ci-split 4: 512 blocks x 288 thr.
    dim3 gh(1, CC / 16, BB);
    for (int wi = 1; wi <= WW - 1; wi++)
        step_kernel<HH, WW, 4, 18, 2, 1, 4, 8, 4><<<gh, 288>>>(T, wi - 1, wi, wt_r, b_r);
    for (int wi = WW - 2; wi >= 1; wi--)
        step_kernel<HH, WW, 4, 18, 2, 1, 4, 8, 4><<<gh, 288>>>(T, wi + 1, wi, wt_l, b_l);

    // ---- Transpose back [B,C,W,H] -> [B,C,H,W] ----
    {
        dim3 tb(32, 8);
        dim3 tg((HH + 31) / 32, (WW + 31) / 32, BB * CC);
        transpose_kernel<<<tg, tb>>>(T, out, WW, HH);
    }
}

// round 3
// speedup vs baseline: 1.4287x; 1.4287x over previous
#include <cuda_runtime.h>
#include <cuda_bf16.h>

// SpatialConv SCNN 4-direction recurrent conv, GB300 sm_103a.
// R3: persistent per-pass kernels + global spin barrier between recurrence
// steps (replaces 266 launches). f32x2 FFMA2 inner loop, dup-SMEM inputs,
// paired weight loads, pre-transposed weights, ci-split for the W pass.

#define BB 64
#define CC 128
#define HH 36
#define WW 100
#define KK 9

typedef unsigned long long u64;

__device__ float g_T[(size_t)BB * CC * WW * HH];     // transposed activations
__device__ float g_Wt[4][CC * CC * KK];              // weights as [ci][k][co]

__device__ u64 g_count = 0;    // barrier arrivals (monotonic, replay-safe)
__device__ u64 g_release = 0;  // barrier epochs released

__device__ __forceinline__ void ffma2(u64& d, u64 a, u64 b) {
    asm("fma.rn.f32x2 %0, %1, %2, %0;" : "+l"(d) : "l"(a), "l"(b));
}
__device__ __forceinline__ u64 pack2(float a, float b) {
    u64 r; asm("mov.b64 %0, {%1, %2};" : "=l"(r) : "f"(a), "f"(b)); return r;
}
__device__ __forceinline__ void unpack2(u64 v, float& a, float& b) {
    asm("mov.b64 {%0, %1}, %2;" : "=f"(a), "=f"(b) : "l"(v));
}

// Grid-wide barrier: all NB blocks arrive, last releases the epoch.
// Monotonic counters -> safe across graph replays without reset.
__device__ __forceinline__ void grid_barrier(unsigned NB) {
    __syncthreads();
    if (threadIdx.x == 0) {
        __threadfence();
        u64 arrived = atomicAdd(&g_count, 1ULL);
        u64 epoch = arrived / NB;
        if (arrived % NB == NB - 1) {
            atomicAdd(&g_release, 1ULL);
        } else {
            int spins = 0;
            while (true) {
                u64 r = *(volatile u64*)&g_release;
                if (r > epoch) break;
                __nanosleep(128);
                if (++spins > (1 << 22)) break;  // bail instead of hanging
            }
        }
        __threadfence();
    }
    __syncthreads();
}

// Persistent pass kernel on buffer [B, C, S, L]. For i in [0, nsteps):
//   s_dst = s_begin + i*dir, s_src = s_dst - dir
//   buf[b,co,s_dst,l] += relu(bias[co] + sum_{ci,k} w[co,ci,k]*buf[b,ci,s_src,l+k-4])
// Grid = (LSPLIT, CC/CO_TILE, BB) blocks; all blocks resident; barrier per step.
template <int L, int S, int CP, int LG, int NL, int LSPLIT, int CIS, int CIC>
__global__ __launch_bounds__(CP * LG * CIS, 4)
void pass_kernel(float* __restrict__ buf,
                 const float* __restrict__ wt, const float* __restrict__ bias,
                 int s_begin, int nsteps, int dir, unsigned NB)
{
    constexpr int CO_TILE = 4 * CP;
    constexpr int LW   = L / LSPLIT;
    constexpr int WIN  = LG * NL + 8;
    constexpr int NT   = CP * LG * CIS;
    constexpr int CI_PER = CC / CIS;
    constexpr int NCHUNK = CI_PER / CIC;
    constexpr int ROWS = CIS * CIC;
    static_assert(LG * NL == LW, "exact L coverage");

    __shared__ __align__(16) float2 in_d[ROWS][WIN];          // {x,x} duplicated
    __shared__ __align__(16) float  w_s[ROWS * KK * CO_TILE]; // [cis][i][k][co]

    const int tid = threadIdx.x;
    const int rr  = tid % (CP * LG);
    const int cis = tid / (CP * LG);
    const int cp  = rr % CP;
    const int lg  = rr / CP;
    const int b   = blockIdx.z;
    const int co_base = blockIdx.y * CO_TILE;
    const int l_base  = blockIdx.x * LW;

    const float b0 = bias[co_base + 4 * cp + 0];
    const float b1 = bias[co_base + 4 * cp + 1];
    const float b2 = bias[co_base + 4 * cp + 2];
    const float b3 = bias[co_base + 4 * cp + 3];
    const u64 bias01 = (cis == 0) ? pack2(b0, b1) : 0ull;
    const u64 bias23 = (cis == 0) ? pack2(b2, b3) : 0ull;

    for (int it = 0; it < nsteps; it++) {
        const int s_dst = s_begin + it * dir;
        const int s_src = s_dst - dir;

        u64 acc0[NL], acc1[NL];
#pragma unroll
        for (int j = 0; j < NL; j++) { acc0[j] = bias01; acc1[j] = bias23; }

        for (int cc = 0; cc < NCHUNK; cc++) {
            __syncthreads();
            // Stage input rows (duplicated floats), zero halo.
            for (int idx = tid; idx < ROWS * WIN; idx += NT) {
                int row = idx / WIN, j = idx % WIN;
                int ciI = row / CIC, i = row % CIC;
                int g = ciI * CI_PER + cc * CIC + i;
                int gl = l_base + j - 4;
                float v = 0.f;
                if (gl >= 0 && gl < L)
                    v = buf[((size_t)(b * CC + g) * S + s_src) * L + gl];
                in_d[row][j] = make_float2(v, v);
            }
            // Stage weights from pre-transposed [ci][k][co].
            for (int idx = tid; idx < ROWS * KK * CO_TILE; idx += NT) {
                int co = idx % CO_TILE;
                int k  = (idx / CO_TILE) % KK;
                int i  = (idx / (CO_TILE * KK)) % CIC;
                int ciI = idx / (CO_TILE * KK * CIC);
                int g = ciI * CI_PER + cc * CIC + i;
                w_s[idx] = wt[((size_t)g * KK + k) * CC + co_base + co];
            }
            __syncthreads();

#pragma unroll 2
            for (int i = 0; i < CIC; i++) {
                const int row = cis * CIC + i;
                u64 xx[NL + 8];
                const u64* xr = (const u64*)&in_d[row][lg * NL];
#pragma unroll
                for (int t = 0; t < NL + 8; t++) xx[t] = xr[t];
                const float* wr = &w_s[(row * KK) * CO_TILE + 4 * cp];
#pragma unroll
                for (int k = 0; k < KK; k++) {
                    ulonglong2 wv = *(const ulonglong2*)(wr + k * CO_TILE);
#pragma unroll
                    for (int j = 0; j < NL; j++) {
                        ffma2(acc0[j], wv.x, xx[j + k]);
                        ffma2(acc1[j], wv.y, xx[j + k]);
                    }
                }
            }
        }
        __syncthreads();

        // Cross-cis reduction through SMEM (reuse w_s region).
        float* red = w_s;
        if (CIS > 1) {
            if (cis > 0) {
                float* p = red + (size_t)(cis - 1) * CO_TILE * LW;
#pragma unroll
                for (int j = 0; j < NL; j++) {
                    int l = lg * NL + j;
                    float a, bb, c, d;
                    unpack2(acc0[j], a, bb); unpack2(acc1[j], c, d);
                    p[(4 * cp + 0) * LW + l] = a;
                    p[(4 * cp + 1) * LW + l] = bb;
                    p[(4 * cp + 2) * LW + l] = c;
                    p[(4 * cp + 3) * LW + l] = d;
                }
            }
            __syncthreads();
        }

        float* out_s = (float*)in_d;
        if (cis == 0) {
#pragma unroll
            for (int j = 0; j < NL; j++) {
                int l = lg * NL + j;
                float a, bb, c, d;
                unpack2(acc0[j], a, bb); unpack2(acc1[j], c, d);
                if (CIS > 1) {
#pragma unroll
                    for (int c2 = 1; c2 < CIS; c2++) {
                        const float* p = red + (size_t)(c2 - 1) * CO_TILE * LW;
                        a  += p[(4 * cp + 0) * LW + l];
                        bb += p[(4 * cp + 1) * LW + l];
                        c  += p[(4 * cp + 2) * LW + l];
                        d  += p[(4 * cp + 3) * LW + l];
                    }
                }
                out_s[(4 * cp + 0) * LW + l] = fmaxf(a, 0.f);
                out_s[(4 * cp + 1) * LW + l] = fmaxf(bb, 0.f);
                out_s[(4 * cp + 2) * LW + l] = fmaxf(c, 0.f);
                out_s[(4 * cp + 3) * LW + l] = fmaxf(d, 0.f);
            }
        }
        __syncthreads();

        for (int idx = tid; idx < CO_TILE * LW; idx += NT) {
            int co = idx / LW, l = idx % LW;
            buf[((size_t)(b * CC + co_base + co) * S + s_dst) * L + l_base + l]
                += out_s[idx];
        }

        grid_barrier(NB);
    }
}

// Weight layout transform: [co][ci][k] -> [ci][k][co]
__global__ void prep_w(const float* __restrict__ w, float* __restrict__ wt) {
    int idx = blockIdx.x * 256 + threadIdx.x;
    if (idx < CC * CC * KK) {
        int co = idx / (CC * KK);
        int rem = idx % (CC * KK);
        int ci = rem / KK, k = rem % KK;
        wt[((size_t)ci * KK + k) * CC + co] = w[idx];
    }
}

// Transpose inner two dims: in [BC][R][Cc] -> out [BC][Cc][R]
__global__ void transpose_kernel(const float* __restrict__ in, float* __restrict__ out,
                                 int R, int Cc)
{
    __shared__ float tile[32][33];
    const int bc = blockIdx.z;
    const int c0 = blockIdx.x * 32;
    const int r0 = blockIdx.y * 32;
    const float* ip = in + (size_t)bc * R * Cc;
    float* op = out + (size_t)bc * R * Cc;
    const int tx = threadIdx.x, ty = threadIdx.y;

    for (int i = ty; i < 32; i += 8) {
        int r = r0 + i, c = c0 + tx;
        if (r < R && c < Cc) tile[i][tx] = ip[(size_t)r * Cc + c];
    }
    __syncthreads();
    for (int i = ty; i < 32; i += 8) {
        int c = c0 + i, r = r0 + tx;
        if (c < Cc && r < R) op[(size_t)c * R + r] = tile[tx][i];
    }
}

extern "C" void kernel_launch(void* const* d_in, const int* in_sizes, int n_in,
                              void* d_out, int out_size)
{
    const float* x   = (const float*)d_in[0];
    const float* w_d = (const float*)d_in[1];
    const float* b_d = (const float*)d_in[2];
    const float* w_u = (const float*)d_in[3];
    const float* b_u = (const float*)d_in[4];
    const float* w_r = (const float*)d_in[5];
    const float* b_r = (const float*)d_in[6];
    const float* w_l = (const float*)d_in[7];
    const float* b_l = (const float*)d_in[8];
    float* out = (float*)d_out;

    float* T = nullptr;
    cudaGetSymbolAddress((void**)&T, g_T);
    float* Wt = nullptr;
    cudaGetSymbolAddress((void**)&Wt, g_Wt);
    float* wt_d = Wt + 0 * (CC * CC * KK);
    float* wt_u = Wt + 1 * (CC * CC * KK);
    float* wt_r = Wt + 2 * (CC * CC * KK);
    float* wt_l = Wt + 3 * (CC * CC * KK);

    const int WG = (CC * CC * KK + 255) / 256;
    prep_w<<<WG, 256>>>(w_d, wt_d);
    prep_w<<<WG, 256>>>(w_u, wt_u);
    prep_w<<<WG, 256>>>(w_r, wt_r);
    prep_w<<<WG, 256>>>(w_l, wt_l);

    const size_t nbytes = (size_t)BB * CC * HH * WW * sizeof(float);
    cudaMemcpyAsync(out, x, nbytes, cudaMemcpyDeviceToDevice, 0);

    // ---- Down / Up passes (persistent): recurrence over H, conv along W ----
    // <L,S,CP,LG,NL,LSPLIT,CIS,CIC> grid (2,4,64)=512 blocks x 200 thr.
    // smem ~13KB/blk, 4 blk/SM guaranteed -> all 512 resident (cap 592).
    {
        dim3 g(2, CC / 32, BB);
        pass_kernel<WW, HH, 8, 25, 2, 2, 1, 8><<<g, 200>>>(out, wt_d, b_d, 1, HH - 1, +1, 512);
        pass_kernel<WW, HH, 8, 25, 2, 2, 1, 8><<<g, 200>>>(out, wt_u, b_u, HH - 2, HH - 2, -1, 512);
    }

    // ---- Transpose [B,C,H,W] -> [B,C,W,H] ----
    {
        dim3 tb(32, 8);
        dim3 tg((WW + 31) / 32, (HH + 31) / 32, BB * CC);
        transpose_kernel<<<tg, tb>>>(out, T, HH, WW);
    }

    // ---- Right / Left passes (persistent): recurrence over W, conv along H ----
    // grid (1,8,64)=512 blocks x 144 thr, ci-split 2. smem ~15KB/blk.
    {
        dim3 g(1, CC / 16, BB);
        pass_kernel<HH, WW, 4, 18, 2, 1, 2, 8><<<g, 144>>>(T, wt_r, b_r, 1, WW - 1, +1, 512);
        pass_kernel<HH, WW, 4, 18, 2, 1, 2, 8><<<g, 144>>>(T, wt_l, b_l, WW - 2, WW - 2, -1, 512);
    }

    // ---- Transpose back [B,C,W,H] -> [B,C,H,W] ----
    {
        dim3 tb(32, 8);
        dim3 tg((HH + 31) / 32, (WW + 31) / 32, BB * CC);
        transpose_kernel<<<tg, tb>>>(T, out, WW, HH);
    }
}

// round 4
// speedup vs baseline: 1.4605x; 1.0223x over previous
#include <cuda_runtime.h>
#include <cuda_bf16.h>

// SpatialConv SCNN 4-direction recurrent conv, GB300 sm_103a.
// R4: per-BATCH spin barriers (8-block scope, 64 independent lines) instead of
// one chip-wide 512-block barrier per recurrence step. Batches drift
// independently -> no global straggler coupling. FFMA2 inner loop unchanged.

#define BB 64
#define CC 128
#define HH 36
#define WW 100
#define KK 9

typedef unsigned long long u64;

__device__ float g_T[(size_t)BB * CC * WW * HH];     // transposed activations
__device__ float g_Wt[4][CC * CC * KK];              // weights as [ci][k][co]

struct __align__(128) BarLine { u64 cnt; u64 rel; u64 pad[14]; };
__device__ BarLine g_bar[BB];   // zero-initialized; monotonic -> replay-safe

__device__ __forceinline__ void ffma2(u64& d, u64 a, u64 b) {
    asm("fma.rn.f32x2 %0, %1, %2, %0;" : "+l"(d) : "l"(a), "l"(b));
}
__device__ __forceinline__ u64 pack2(float a, float b) {
    u64 r; asm("mov.b64 %0, {%1, %2};" : "=l"(r) : "f"(a), "f"(b)); return r;
}
__device__ __forceinline__ void unpack2(u64 v, float& a, float& b) {
    asm("mov.b64 {%0, %1}, %2;" : "=f"(a), "=f"(b) : "l"(v));
}

// Per-batch barrier: NB blocks of the same batch arrive; last releases epoch.
template <int NB>
__device__ __forceinline__ void batch_barrier(int b) {
    __syncthreads();
    if (threadIdx.x == 0) {
        __threadfence();
        u64 arrived = atomicAdd(&g_bar[b].cnt, 1ULL);
        u64 epoch = arrived / NB;
        if (arrived % NB == (u64)(NB - 1)) {
            atomicAdd(&g_bar[b].rel, 1ULL);
        } else {
            unsigned spins = 0;
            while (*(volatile u64*)&g_bar[b].rel <= epoch) {
                if ((++spins & 63u) == 0) __nanosleep(32);
                if (spins > (1u << 26)) break;   // bail, never hang
            }
        }
        __threadfence();
    }
    __syncthreads();
}

// Persistent pass kernel on buffer [B, C, S, L]. For i in [0, nsteps):
//   s_dst = s_begin + i*dir, s_src = s_dst - dir
//   buf[b,co,s_dst,l] += relu(bias[co] + sum_{ci,k} w[co,ci,k]*buf[b,ci,s_src,l+k-4])
// Grid = (LSPLIT, CC/CO_TILE, BB); per-batch sync scope = LSPLIT*CC/CO_TILE.
template <int L, int S, int CP, int LG, int NL, int LSPLIT, int CIS, int CIC>
__global__ __launch_bounds__(CP * LG * CIS, 4)
void pass_kernel(float* __restrict__ buf,
                 const float* __restrict__ wt, const float* __restrict__ bias,
                 int s_begin, int nsteps, int dir)
{
    constexpr int CO_TILE = 4 * CP;
    constexpr int LW   = L / LSPLIT;
    constexpr int WIN  = LG * NL + 8;
    constexpr int NT   = CP * LG * CIS;
    constexpr int CI_PER = CC / CIS;
    constexpr int NCHUNK = CI_PER / CIC;
    constexpr int ROWS = CIS * CIC;
    constexpr int NB   = LSPLIT * (CC / CO_TILE);   // blocks per batch
    static_assert(LG * NL == LW, "exact L coverage");

    __shared__ __align__(16) float2 in_d[ROWS][WIN];          // {x,x} duplicated
    __shared__ __align__(16) float  w_s[ROWS * KK * CO_TILE]; // [cis][i][k][co]

    const int tid = threadIdx.x;
    const int rr  = tid % (CP * LG);
    const int cis = tid / (CP * LG);
    const int cp  = rr % CP;
    const int lg  = rr / CP;
    const int b   = blockIdx.z;
    const int co_base = blockIdx.y * CO_TILE;
    const int l_base  = blockIdx.x * LW;

    const float b0 = bias[co_base + 4 * cp + 0];
    const float b1 = bias[co_base + 4 * cp + 1];
    const float b2 = bias[co_base + 4 * cp + 2];
    const float b3 = bias[co_base + 4 * cp + 3];
    const u64 bias01 = (cis == 0) ? pack2(b0, b1) : 0ull;
    const u64 bias23 = (cis == 0) ? pack2(b2, b3) : 0ull;

    for (int it = 0; it < nsteps; it++) {
        const int s_dst = s_begin + it * dir;
        const int s_src = s_dst - dir;

        u64 acc0[NL], acc1[NL];
#pragma unroll
        for (int j = 0; j < NL; j++) { acc0[j] = bias01; acc1[j] = bias23; }

        for (int cc = 0; cc < NCHUNK; cc++) {
            __syncthreads();
            // Stage input rows (duplicated floats), zero halo.
            for (int idx = tid; idx < ROWS * WIN; idx += NT) {
                int row = idx / WIN, j = idx % WIN;
                int ciI = row / CIC, i = row % CIC;
                int g = ciI * CI_PER + cc * CIC + i;
                int gl = l_base + j - 4;
                float v = 0.f;
                if (gl >= 0 && gl < L)
                    v = buf[((size_t)(b * CC + g) * S + s_src) * L + gl];
                in_d[row][j] = make_float2(v, v);
            }
            // Stage weights from pre-transposed [ci][k][co].
            for (int idx = tid; idx < ROWS * KK * CO_TILE; idx += NT) {
                int co = idx % CO_TILE;
                int k  = (idx / CO_TILE) % KK;
                int i  = (idx / (CO_TILE * KK)) % CIC;
                int ciI = idx / (CO_TILE * KK * CIC);
                int g = ciI * CI_PER + cc * CIC + i;
                w_s[idx] = wt[((size_t)g * KK + k) * CC + co_base + co];
            }
            __syncthreads();

#pragma unroll 2
            for (int i = 0; i < CIC; i++) {
                const int row = cis * CIC + i;
                u64 xx[NL + 8];
                const u64* xr = (const u64*)&in_d[row][lg * NL];
#pragma unroll
                for (int t = 0; t < NL + 8; t++) xx[t] = xr[t];
                const float* wr = &w_s[(row * KK) * CO_TILE + 4 * cp];
#pragma unroll
                for (int k = 0; k < KK; k++) {
                    ulonglong2 wv = *(const ulonglong2*)(wr + k * CO_TILE);
#pragma unroll
                    for (int j = 0; j < NL; j++) {
                        ffma2(acc0[j], wv.x, xx[j + k]);
                        ffma2(acc1[j], wv.y, xx[j + k]);
                    }
                }
            }
        }
        __syncthreads();

        // Cross-cis reduction through SMEM (reuse w_s region).
        float* red = w_s;
        if (CIS > 1) {
            if (cis > 0) {
                float* p = red + (size_t)(cis - 1) * CO_TILE * LW;
#pragma unroll
                for (int j = 0; j < NL; j++) {
                    int l = lg * NL + j;
                    float a, bb, c, d;
                    unpack2(acc0[j], a, bb); unpack2(acc1[j], c, d);
                    p[(4 * cp + 0) * LW + l] = a;
                    p[(4 * cp + 1) * LW + l] = bb;
                    p[(4 * cp + 2) * LW + l] = c;
                    p[(4 * cp + 3) * LW + l] = d;
                }
            }
            __syncthreads();
        }

        float* out_s = (float*)in_d;
        if (cis == 0) {
#pragma unroll
            for (int j = 0; j < NL; j++) {
                int l = lg * NL + j;
                float a, bb, c, d;
                unpack2(acc0[j], a, bb); unpack2(acc1[j], c, d);
                if (CIS > 1) {
#pragma unroll
                    for (int c2 = 1; c2 < CIS; c2++) {
                        const float* p = red + (size_t)(c2 - 1) * CO_TILE * LW;
                        a  += p[(4 * cp + 0) * LW + l];
                        bb += p[(4 * cp + 1) * LW + l];
                        c  += p[(4 * cp + 2) * LW + l];
                        d  += p[(4 * cp + 3) * LW + l];
                    }
                }
                out_s[(4 * cp + 0) * LW + l] = fmaxf(a, 0.f);
                out_s[(4 * cp + 1) * LW + l] = fmaxf(bb, 0.f);
                out_s[(4 * cp + 2) * LW + l] = fmaxf(c, 0.f);
                out_s[(4 * cp + 3) * LW + l] = fmaxf(d, 0.f);
            }
        }
        __syncthreads();

        for (int idx = tid; idx < CO_TILE * LW; idx += NT) {
            int co = idx / LW, l = idx % LW;
            buf[((size_t)(b * CC + co_base + co) * S + s_dst) * L + l_base + l]
                += out_s[idx];
        }

        batch_barrier<NB>(b);
    }
}

// Weight layout transform for all 4 weight sets: [co][ci][k] -> [ci][k][co]
__global__ void prep_w4(const float* __restrict__ w0, const float* __restrict__ w1,
                        const float* __restrict__ w2, const float* __restrict__ w3,
                        float* __restrict__ wt)
{
    int idx = blockIdx.x * 256 + threadIdx.x;
    if (idx < CC * CC * KK) {
        int co = idx / (CC * KK);
        int rem = idx % (CC * KK);
        int ci = rem / KK, k = rem % KK;
        size_t o = ((size_t)ci * KK + k) * CC + co;
        const size_t SZ = (size_t)CC * CC * KK;
        wt[o] = w0[idx];
        wt[SZ + o] = w1[idx];
        wt[2 * SZ + o] = w2[idx];
        wt[3 * SZ + o] = w3[idx];
    }
}

// Transpose inner two dims: in [BC][R][Cc] -> out [BC][Cc][R]
__global__ void transpose_kernel(const float* __restrict__ in, float* __restrict__ out,
                                 int R, int Cc)
{
    __shared__ float tile[32][33];
    const int bc = blockIdx.z;
    const int c0 = blockIdx.x * 32;
    const int r0 = blockIdx.y * 32;
    const float* ip = in + (size_t)bc * R * Cc;
    float* op = out + (size_t)bc * R * Cc;
    const int tx = threadIdx.x, ty = threadIdx.y;

    for (int i = ty; i < 32; i += 8) {
        int r = r0 + i, c = c0 + tx;
        if (r < R && c < Cc) tile[i][tx] = ip[(size_t)r * Cc + c];
    }
    __syncthreads();
    for (int i = ty; i < 32; i += 8) {
        int c = c0 + i, r = r0 + tx;
        if (c < Cc && r < R) op[(size_t)c * R + r] = tile[tx][i];
    }
}

extern "C" void kernel_launch(void* const* d_in, const int* in_sizes, int n_in,
                              void* d_out, int out_size)
{
    const float* x   = (const float*)d_in[0];
    const float* w_d = (const float*)d_in[1];
    const float* b_d = (const float*)d_in[2];
    const float* w_u = (const float*)d_in[3];
    const float* b_u = (const float*)d_in[4];
    const float* w_r = (const float*)d_in[5];
    const float* b_r = (const float*)d_in[6];
    const float* w_l = (const float*)d_in[7];
    const float* b_l = (const float*)d_in[8];
    float* out = (float*)d_out;

    float* T = nullptr;
    cudaGetSymbolAddress((void**)&T, g_T);
    float* Wt = nullptr;
    cudaGetSymbolAddress((void**)&Wt, g_Wt);
    const size_t SZ = (size_t)CC * CC * KK;
    float* wt_d = Wt;
    float* wt_u = Wt + SZ;
    float* wt_r = Wt + 2 * SZ;
    float* wt_l = Wt + 3 * SZ;

    const int WG = (CC * CC * KK + 255) / 256;
    prep_w4<<<WG, 256>>>(w_d, w_u, w_r, w_l, Wt);

    const size_t nbytes = (size_t)BB * CC * HH * WW * sizeof(float);
    cudaMemcpyAsync(out, x, nbytes, cudaMemcpyDeviceToDevice, 0);

    // ---- Down / Up passes: recurrence over H, conv along W ----
    // grid (2,4,64)=512 blocks x 200 thr; sync scope = 8 blocks per batch.
    {
        dim3 g(2, CC / 32, BB);
        pass_kernel<WW, HH, 8, 25, 2, 2, 1, 8><<<g, 200>>>(out, wt_d, b_d, 1, HH - 1, +1);
        pass_kernel<WW, HH, 8, 25, 2, 2, 1, 8><<<g, 200>>>(out, wt_u, b_u, HH - 2, HH - 2, -1);
    }

    // ---- Transpose [B,C,H,W] -> [B,C,W,H] ----
    {
        dim3 tb(32, 8);
        dim3 tg((WW + 31) / 32, (HH + 31) / 32, BB * CC);
        transpose_kernel<<<tg, tb>>>(out, T, HH, WW);
    }

    // ---- Right / Left passes: recurrence over W, conv along H ----
    // grid (1,8,64)=512 blocks x 144 thr; sync scope = 8 blocks per batch.
    {
        dim3 g(1, CC / 16, BB);
        pass_kernel<HH, WW, 4, 18, 2, 1, 2, 8><<<g, 144>>>(T, wt_r, b_r, 1, WW - 1, +1);
        pass_kernel<HH, WW, 4, 18, 2, 1, 2, 8><<<g, 144>>>(T, wt_l, b_l, WW - 2, WW - 2, -1);
    }

    // ---- Transpose back [B,C,W,H] -> [B,C,H,W] ----
    {
        dim3 tb(32, 8);
        dim3 tg((HH + 31) / 32, (WW + 31) / 32, BB * CC);
        transpose_kernel<<<tg, tb>>>(T, out, WW, HH);
    }
}

// round 5
// speedup vs baseline: 2.8787x; 1.9710x over previous
#include <cuda_runtime.h>
#include <cuda_bf16.h>

// SpatialConv SCNN 4-direction recurrent conv, GB300 sm_103a.
// R5: 128 persistent blocks (4 co-quarters x 32 batch-pairs), one per SM.
// Full weight slice resident in SMEM (loaded once per pass). Double-buffered
// input staging. FFMA2 inner loop, NL=5 (H) / NL=3+ci-split2 (W).

#define BB 64
#define CC 128
#define HH 36
#define WW 100
#define KK 9

typedef unsigned long long u64;

__device__ float g_T[(size_t)BB * CC * WW * HH];   // transposed activations
__device__ float g_Wt[4][CC * CC * KK];            // weights as [ci*9+k][co]

struct __align__(128) BarLine { u64 cnt; u64 rel; u64 pad[14]; };
__device__ BarLine g_bar[32];  // zero-init; monotonic -> replay-safe

__device__ __forceinline__ void ffma2(u64& d, u64 a, u64 b) {
    asm("fma.rn.f32x2 %0, %1, %2, %0;" : "+l"(d) : "l"(a), "l"(b));
}
__device__ __forceinline__ u64 pack2(float a, float b) {
    u64 r; asm("mov.b64 %0, {%1, %2};" : "=l"(r) : "f"(a), "f"(b)); return r;
}
__device__ __forceinline__ void unpack2(u64 v, float& a, float& b) {
    asm("mov.b64 {%0, %1}, %2;" : "=f"(a), "=f"(b) : "l"(v));
}

// Group barrier: NB blocks of one batch-pair group arrive; last releases.
// __threadfence() (gpu scope) also flushes L1D -> cross-SM data freshness.
template <int NB>
__device__ __forceinline__ void group_barrier(int gid) {
    __syncthreads();
    if (threadIdx.x == 0) {
        __threadfence();
        u64 arrived = atomicAdd(&g_bar[gid].cnt, 1ULL);
        u64 epoch = arrived / NB;
        if (arrived % NB == (u64)(NB - 1)) {
            atomicAdd(&g_bar[gid].rel, 1ULL);
        } else {
            unsigned spins = 0;
            while (*(volatile u64*)&g_bar[gid].rel <= epoch) {
                if ((++spins & 63u) == 0) __nanosleep(32);
                if (spins > (1u << 26)) break;   // bail, never hang
            }
        }
        __threadfence();
    }
    __syncthreads();
}

// Persistent pass kernel on buffer [B, C, S, L].
// Block = (co-quarter, batch-pair). Weights SMEM-resident for the whole pass.
// Thread map: tid = lg + LG*(cp + CP*(bsel + 2*cis)); 4 co x NL l per thread.
template <int L, int S, int CP, int LG, int NL, int CIS>
__global__ __launch_bounds__(2 * CP * LG * CIS, 1)
void pass_kernel(float* __restrict__ buf,
                 const float* __restrict__ wt, const float* __restrict__ bias,
                 int s_begin, int nsteps, int dir)
{
    constexpr int CO_TILE = 4 * CP;                 // 32
    constexpr int WIN  = LG * NL + 8;
    constexpr int NT   = 2 * CP * LG * CIS;
    constexpr int CIC  = 16;                        // rows staged per chunk
    constexpr int NCHUNK = CC / CIC;                // 8
    constexpr int RPC  = CIC / CIS;                 // rows per cis per chunk
    constexpr int TOT  = 2 * CIC * WIN;             // staged floats per chunk
    constexpr int NPRE = (TOT + NT - 1) / NT;
    static_assert(LG * NL == L, "full L coverage");

    extern __shared__ __align__(16) char smem_raw[];
    float*  w_all = (float*)smem_raw;                          // CC*KK*CO_TILE
    float2* in_d  = (float2*)(smem_raw + (size_t)CC * KK * CO_TILE * 4);
    float*  red   = (float*)in_d;                              // CIS=2 partials

    const int tid  = threadIdx.x;
    const int lg   = tid % LG;
    const int cp   = (tid / LG) % CP;
    const int bsel = (tid / (LG * CP)) % 2;
    const int cis  = tid / (LG * CP * 2);
    const int b0   = blockIdx.y * 2;
    const int co_base = blockIdx.x * CO_TILE;
    const int gid  = blockIdx.y;

    // Load full weight slice once: w_all[(ci*9+k)*32 + co].
    for (int idx = tid; idx < CC * KK * CO_TILE; idx += NT)
        w_all[idx] = wt[(size_t)(idx / CO_TILE) * CC + co_base + (idx % CO_TILE)];

    u64 bias01, bias23;
    {
        float v0 = bias[co_base + 4 * cp + 0];
        float v1 = bias[co_base + 4 * cp + 1];
        float v2 = bias[co_base + 4 * cp + 2];
        float v3 = bias[co_base + 4 * cp + 3];
        bias01 = (cis == 0) ? pack2(v0, v1) : 0ull;
        bias23 = (cis == 0) ? pack2(v2, v3) : 0ull;
    }
    __syncthreads();

    for (int it = 0; it < nsteps; it++) {
        const int s_dst = s_begin + it * dir;
        const int s_src = s_dst - dir;

        // ---- stage chunk 0 into buffer 0 ----
        for (int idx = tid; idx < TOT; idx += NT) {
            int bs = idx / (CIC * WIN);
            int rem = idx % (CIC * WIN);
            int r = rem / WIN, j = rem % WIN;
            int ci = (r / RPC) * (CC / CIS) + 0 * RPC + (r % RPC);
            int gl = j - 4;
            float v = 0.f;
            if (gl >= 0 && gl < L)
                v = buf[((size_t)((b0 + bs) * CC + ci) * S + s_src) * L + gl];
            in_d[((bs * 2 + 0) * CIC + r) * WIN + j] = make_float2(v, v);
        }
        __syncthreads();

        u64 acc0[NL], acc1[NL];
#pragma unroll
        for (int j = 0; j < NL; j++) { acc0[j] = bias01; acc1[j] = bias23; }

        for (int c = 0; c < NCHUNK; c++) {
            const int p = c & 1;
            // Prefetch chunk c+1 loads into registers (latency overlaps compute).
            float pre[NPRE];
            if (c < NCHUNK - 1) {
#pragma unroll
                for (int ii = 0; ii < NPRE; ii++) {
                    int idx = tid + ii * NT;
                    if (idx < TOT) {
                        int bs = idx / (CIC * WIN);
                        int rem = idx % (CIC * WIN);
                        int r = rem / WIN, j = rem % WIN;
                        int ci = (r / RPC) * (CC / CIS) + (c + 1) * RPC + (r % RPC);
                        int gl = j - 4;
                        float v = 0.f;
                        if (gl >= 0 && gl < L)
                            v = buf[((size_t)((b0 + bs) * CC + ci) * S + s_src) * L + gl];
                        pre[ii] = v;
                    }
                }
            }
            // Compute chunk c.
#pragma unroll 2
            for (int r = cis * RPC; r < cis * RPC + RPC; r++) {
                const int ci = (r / RPC) * (CC / CIS) + c * RPC + (r % RPC);
                u64 xx[NL + 8];
                const u64* xr = (const u64*)&in_d[((bsel * 2 + p) * CIC + r) * WIN + lg * NL];
#pragma unroll
                for (int t = 0; t < NL + 8; t++) xx[t] = xr[t];
                const float* wr = &w_all[(size_t)(ci * KK) * CO_TILE + 4 * cp];
#pragma unroll
                for (int k = 0; k < KK; k++) {
                    ulonglong2 wv = *(const ulonglong2*)(wr + k * CO_TILE);
#pragma unroll
                    for (int j = 0; j < NL; j++) {
                        ffma2(acc0[j], wv.x, xx[j + k]);
                        ffma2(acc1[j], wv.y, xx[j + k]);
                    }
                }
            }
            if (c < NCHUNK - 1) {
                // Store prefetched chunk c+1 into the other buffer.
#pragma unroll
                for (int ii = 0; ii < NPRE; ii++) {
                    int idx = tid + ii * NT;
                    if (idx < TOT) {
                        int bs = idx / (CIC * WIN);
                        int rem = idx % (CIC * WIN);
                        int r = rem / WIN, j = rem % WIN;
                        in_d[((bs * 2 + (p ^ 1)) * CIC + r) * WIN + j] =
                            make_float2(pre[ii], pre[ii]);
                    }
                }
                __syncthreads();
            }
        }
        __syncthreads();

        if (CIS == 2) {
            if (cis == 1) {
#pragma unroll
                for (int j = 0; j < NL; j++) {
                    int l = lg * NL + j;
                    float a, bb, cv, d;
                    unpack2(acc0[j], a, bb); unpack2(acc1[j], cv, d);
                    float* p = &red[(size_t)(bsel * CO_TILE) * L];
                    p[(4 * cp + 0) * L + l] = a;
                    p[(4 * cp + 1) * L + l] = bb;
                    p[(4 * cp + 2) * L + l] = cv;
                    p[(4 * cp + 3) * L + l] = d;
                }
            }
            __syncthreads();
        }

        if (cis == 0) {
#pragma unroll
            for (int j = 0; j < NL; j++) {
                int l = lg * NL + j;
                float a, bb, cv, d;
                unpack2(acc0[j], a, bb); unpack2(acc1[j], cv, d);
                if (CIS == 2) {
                    const float* p = &red[(size_t)(bsel * CO_TILE) * L];
                    a  += p[(4 * cp + 0) * L + l];
                    bb += p[(4 * cp + 1) * L + l];
                    cv += p[(4 * cp + 2) * L + l];
                    d  += p[(4 * cp + 3) * L + l];
                }
                size_t base = ((size_t)((b0 + bsel) * CC + co_base + 4 * cp) * S + s_dst) * L + l;
                buf[base + 0 * S * L] += fmaxf(a, 0.f);
                buf[base + 1 * S * L] += fmaxf(bb, 0.f);
                buf[base + 2 * S * L] += fmaxf(cv, 0.f);
                buf[base + 3 * S * L] += fmaxf(d, 0.f);
            }
        }

        group_barrier<4>(gid);
    }
}

// Weight layout transform for all 4 sets: [co][ci][k] -> [ci*9+k][co]
__global__ void prep_w4(const float* __restrict__ w0, const float* __restrict__ w1,
                        const float* __restrict__ w2, const float* __restrict__ w3,
                        float* __restrict__ wt)
{
    int idx = blockIdx.x * 256 + threadIdx.x;
    if (idx < CC * CC * KK) {
        int co = idx / (CC * KK);
        int rem = idx % (CC * KK);
        int ci = rem / KK, k = rem % KK;
        size_t o = ((size_t)ci * KK + k) * CC + co;
        const size_t SZ = (size_t)CC * CC * KK;
        wt[o] = w0[idx];
        wt[SZ + o] = w1[idx];
        wt[2 * SZ + o] = w2[idx];
        wt[3 * SZ + o] = w3[idx];
    }
}

// Transpose inner two dims: in [BC][R][Cc] -> out [BC][Cc][R]
__global__ void transpose_kernel(const float* __restrict__ in, float* __restrict__ out,
                                 int R, int Cc)
{
    __shared__ float tile[32][33];
    const int bc = blockIdx.z;
    const int c0 = blockIdx.x * 32;
    const int r0 = blockIdx.y * 32;
    const float* ip = in + (size_t)bc * R * Cc;
    float* op = out + (size_t)bc * R * Cc;
    const int tx = threadIdx.x, ty = threadIdx.y;

    for (int i = ty; i < 32; i += 8) {
        int r = r0 + i, c = c0 + tx;
        if (r < R && c < Cc) tile[i][tx] = ip[(size_t)r * Cc + c];
    }
    __syncthreads();
    for (int i = ty; i < 32; i += 8) {
        int c = c0 + i, r = r0 + tx;
        if (c < Cc && r < R) op[(size_t)c * R + r] = tile[tx][i];
    }
}

extern "C" void kernel_launch(void* const* d_in, const int* in_sizes, int n_in,
                              void* d_out, int out_size)
{
    const float* x   = (const float*)d_in[0];
    const float* w_d = (const float*)d_in[1];
    const float* b_d = (const float*)d_in[2];
    const float* w_u = (const float*)d_in[3];
    const float* b_u = (const float*)d_in[4];
    const float* w_r = (const float*)d_in[5];
    const float* b_r = (const float*)d_in[6];
    const float* w_l = (const float*)d_in[7];
    const float* b_l = (const float*)d_in[8];
    float* out = (float*)d_out;

    float* T = nullptr;
    cudaGetSymbolAddress((void**)&T, g_T);
    float* Wt = nullptr;
    cudaGetSymbolAddress((void**)&Wt, g_Wt);
    const size_t SZ = (size_t)CC * CC * KK;
    float* wt_d = Wt;
    float* wt_u = Wt + SZ;
    float* wt_r = Wt + 2 * SZ;
    float* wt_l = Wt + 3 * SZ;

    const int WG = (CC * CC * KK + 255) / 256;
    prep_w4<<<WG, 256>>>(w_d, w_u, w_r, w_l, Wt);

    const size_t nbytes = (size_t)BB * CC * HH * WW * sizeof(float);
    cudaMemcpyAsync(out, x, nbytes, cudaMemcpyDeviceToDevice, 0);

    // ---- H passes (down/up): conv along W (L=100, S=36) ----
    // <L,S,CP,LG,NL,CIS> = <100,36,8,20,5,1>: 320 thr, smem 144K(w)+54K(in).
    {
        constexpr int SMEM_H = CC * KK * 32 * 4 + 2 * 2 * 16 * (20 * 5 + 8) * 8;
        cudaFuncSetAttribute(pass_kernel<WW, HH, 8, 20, 5, 1>,
                             cudaFuncAttributeMaxDynamicSharedMemorySize, SMEM_H);
        dim3 g(4, 32);
        pass_kernel<WW, HH, 8, 20, 5, 1><<<g, 320, SMEM_H>>>(out, wt_d, b_d, 1, HH - 1, +1);
        pass_kernel<WW, HH, 8, 20, 5, 1><<<g, 320, SMEM_H>>>(out, wt_u, b_u, HH - 2, HH - 2, -1);
    }

    // ---- Transpose [B,C,H,W] -> [B,C,W,H] ----
    {
        dim3 tb(32, 8);
        dim3 tg((WW + 31) / 32, (HH + 31) / 32, BB * CC);
        transpose_kernel<<<tg, tb>>>(out, T, HH, WW);
    }

    // ---- W passes (right/left): conv along H (L=36, S=100), ci-split 2 ----
    // <36,100,8,12,3,2>: 384 thr, smem 144K(w)+22K(in).
    {
        constexpr int SMEM_W = CC * KK * 32 * 4 + 2 * 2 * 16 * (12 * 3 + 8) * 8;
        cudaFuncSetAttribute(pass_kernel<HH, WW, 8, 12, 3, 2>,
                             cudaFuncAttributeMaxDynamicSharedMemorySize, SMEM_W);
        dim3 g(4, 32);
        pass_kernel<HH, WW, 8, 12, 3, 2><<<g, 384, SMEM_W>>>(T, wt_r, b_r, 1, WW - 1, +1);
        pass_kernel<HH, WW, 8, 12, 3, 2><<<g, 384, SMEM_W>>>(T, wt_l, b_l, WW - 2, WW - 2, -1);
    }

    // ---- Transpose back [B,C,W,H] -> [B,C,H,W] ----
    {
        dim3 tb(32, 8);
        dim3 tg((HH + 31) / 32, (WW + 31) / 32, BB * CC);
        transpose_kernel<<<tg, tb>>>(T, out, WW, HH);
    }
}